// round 9
// baseline (speedup 1.0000x reference)
#include <cuda_runtime.h>

#define Bq 4
#define Hq 16
#define Sq 4096
#define Dq 64
#define BHq (Bq*Hq)            // 64

#define SPLIT1 16
#define CHUNK1 (Sq/SPLIT1)     // 256 rows per pass-1 block
#define TILE1  32              // rows (16 s-pairs) per staged tile
#define NIT1   (CHUNK1/TILE1)  // 8
#define NPART  SPLIT1

#define SPLIT3 16
#define CHUNK3 (Sq/SPLIT3)     // 256
#define SLAB3  64
#define NSL3   (CHUNK3/SLAB3)  // 4

__device__ float g_part[NPART][BHq][Dq*Dq];
__device__ float g_k1p [SPLIT1][BHq][Dq];
__device__ float g_kv[BHq][Dq*Dq];
__device__ float g_k1[BHq][Dq];

typedef unsigned long long u64;

__device__ __forceinline__ void fma2(u64 &d, u64 a, u64 b) {
    asm("fma.rn.f32x2 %0, %1, %2, %0;" : "+l"(d) : "l"(a), "l"(b));
}
__device__ __forceinline__ float2 up2(u64 v) {
    float2 f;
    asm("mov.b64 {%0, %1}, %2;" : "=f"(f.x), "=f"(f.y) : "l"(v));
    return f;
}
__device__ __forceinline__ float phif(float x) {
    return x > 0.f ? x + 1.f : __expf(x);
}
#define SCALE 0.3535533905932738f  // 1/sqrt(sqrt(64))

// ---------------------------------------------------------------------------
// Pass 1: kv[d][e] partials. FFMA2 packed along s (s-pairs).
// 256 thr = 16 d-thr x 16 e-thr, thread tile 4d x 4e (32-reg accumulator).
// Double-buffered smem, 1 barrier/tile, LDG(i+1) issued before compute(i).
// __launch_bounds__(256,3) -> 3 blocks/SM (24 warps) for latency hiding.
// ---------------------------------------------------------------------------
__global__ void __launch_bounds__(256, 3)
k1_partial(const float* __restrict__ K, const float* __restrict__ V,
           const float* __restrict__ mask)
{
    __shared__ __align__(16) float2 ks2[2][TILE1/2][Dq];  // 16 KB
    __shared__ __align__(16) float2 vs2[2][TILE1/2][Dq];  // 16 KB
    __shared__ float k1buf[Dq][17];

    const int t  = threadIdx.x;
    const int bh = blockIdx.x & (BHq - 1);
    const int sp = blockIdx.x >> 6;
    const int b  = bh >> 4;
    const int s0 = sp * CHUNK1;

    const int p  = t >> 4;              // staged s-pair 0..15
    const int dg = (t & 15) << 2;       // staged col base
    const int d0 = (t >> 4) << 2;       // accum d base (16 d-threads)
    const int eb = (t & 15) << 2;       // accum e base (16 e-threads)

    u64 acc[4][4];
#pragma unroll
    for (int i = 0; i < 4; i++)
#pragma unroll
        for (int j = 0; j < 4; j++) acc[i][j] = 0ull;
    float2 k1a[4] = {{0.f,0.f},{0.f,0.f},{0.f,0.f},{0.f,0.f}};

    const float* Kb = K + (size_t)bh * Sq * Dq;
    const float* Vb = V + (size_t)bh * Sq * Dq;
    const float* Mb = mask + (size_t)b * Sq;

    float4 ka, kb, va, vb;
    float ma, mb2;

    // prologue: load + stage tile 0
    {
        const int sa = s0 + 2 * p;
        ka = *(const float4*)(Kb + (size_t)sa * Dq + dg);
        kb = *(const float4*)(Kb + (size_t)(sa + 1) * Dq + dg);
        va = *(const float4*)(Vb + (size_t)sa * Dq + dg);
        vb = *(const float4*)(Vb + (size_t)(sa + 1) * Dq + dg);
        ma = Mb[sa]; mb2 = Mb[sa + 1];
    }
    {
        float2 P0 = make_float2(phif(ka.x*SCALE)*ma, phif(kb.x*SCALE)*mb2);
        float2 P1 = make_float2(phif(ka.y*SCALE)*ma, phif(kb.y*SCALE)*mb2);
        float2 P2 = make_float2(phif(ka.z*SCALE)*ma, phif(kb.z*SCALE)*mb2);
        float2 P3 = make_float2(phif(ka.w*SCALE)*ma, phif(kb.w*SCALE)*mb2);
        k1a[0].x += P0.x; k1a[0].y += P0.y; k1a[1].x += P1.x; k1a[1].y += P1.y;
        k1a[2].x += P2.x; k1a[2].y += P2.y; k1a[3].x += P3.x; k1a[3].y += P3.y;
        *(float4*)&ks2[0][p][dg]     = make_float4(P0.x,P0.y,P1.x,P1.y);
        *(float4*)&ks2[0][p][dg + 2] = make_float4(P2.x,P2.y,P3.x,P3.y);
        *(float4*)&vs2[0][p][dg]     = make_float4(va.x,vb.x,va.y,vb.y);
        *(float4*)&vs2[0][p][dg + 2] = make_float4(va.z,vb.z,va.w,vb.w);
    }

#pragma unroll 1
    for (int it = 0; it < NIT1; it++) {
        __syncthreads();   // buf[it&1] ready; buf[(it+1)&1] free

        if (it + 1 < NIT1) {     // issue gmem loads for next tile
            const int sa = s0 + (it + 1) * TILE1 + 2 * p;
            ka = *(const float4*)(Kb + (size_t)sa * Dq + dg);
            kb = *(const float4*)(Kb + (size_t)(sa + 1) * Dq + dg);
            va = *(const float4*)(Vb + (size_t)sa * Dq + dg);
            vb = *(const float4*)(Vb + (size_t)(sa + 1) * Dq + dg);
            ma = Mb[sa]; mb2 = Mb[sa + 1];
        }

        const int bf = it & 1;
#pragma unroll
        for (int s2 = 0; s2 < TILE1/2; s2++) {
            const ulonglong2 A01 = *(const ulonglong2*)&ks2[bf][s2][d0];
            const ulonglong2 A23 = *(const ulonglong2*)&ks2[bf][s2][d0 + 2];
            const ulonglong2 B01 = *(const ulonglong2*)&vs2[bf][s2][eb];
            const ulonglong2 B23 = *(const ulonglong2*)&vs2[bf][s2][eb + 2];
            fma2(acc[0][0], A01.x, B01.x); fma2(acc[0][1], A01.x, B01.y);
            fma2(acc[0][2], A01.x, B23.x); fma2(acc[0][3], A01.x, B23.y);
            fma2(acc[1][0], A01.y, B01.x); fma2(acc[1][1], A01.y, B01.y);
            fma2(acc[1][2], A01.y, B23.x); fma2(acc[1][3], A01.y, B23.y);
            fma2(acc[2][0], A23.x, B01.x); fma2(acc[2][1], A23.x, B01.y);
            fma2(acc[2][2], A23.x, B23.x); fma2(acc[2][3], A23.x, B23.y);
            fma2(acc[3][0], A23.y, B01.x); fma2(acc[3][1], A23.y, B01.y);
            fma2(acc[3][2], A23.y, B23.x); fma2(acc[3][3], A23.y, B23.y);
        }

        if (it + 1 < NIT1) {     // phi + stage next tile into other buffer
            const int nb = (it + 1) & 1;
            float2 P0 = make_float2(phif(ka.x*SCALE)*ma, phif(kb.x*SCALE)*mb2);
            float2 P1 = make_float2(phif(ka.y*SCALE)*ma, phif(kb.y*SCALE)*mb2);
            float2 P2 = make_float2(phif(ka.z*SCALE)*ma, phif(kb.z*SCALE)*mb2);
            float2 P3 = make_float2(phif(ka.w*SCALE)*ma, phif(kb.w*SCALE)*mb2);
            k1a[0].x += P0.x; k1a[0].y += P0.y; k1a[1].x += P1.x; k1a[1].y += P1.y;
            k1a[2].x += P2.x; k1a[2].y += P2.y; k1a[3].x += P3.x; k1a[3].y += P3.y;
            *(float4*)&ks2[nb][p][dg]     = make_float4(P0.x,P0.y,P1.x,P1.y);
            *(float4*)&ks2[nb][p][dg + 2] = make_float4(P2.x,P2.y,P3.x,P3.y);
            *(float4*)&vs2[nb][p][dg]     = make_float4(va.x,vb.x,va.y,vb.y);
            *(float4*)&vs2[nb][p][dg + 2] = make_float4(va.z,vb.z,va.w,vb.w);
        }
    }

    // kv partial epilogue (horizontal add of s-pair halves)
    float* dst = &g_part[sp][bh][0];
#pragma unroll
    for (int i = 0; i < 4; i++) {
        const float2 a0 = up2(acc[i][0]);
        const float2 a1 = up2(acc[i][1]);
        const float2 a2 = up2(acc[i][2]);
        const float2 a3 = up2(acc[i][3]);
        *(float4*)&dst[(d0 + i) * Dq + eb] =
            make_float4(a0.x + a0.y, a1.x + a1.y, a2.x + a2.y, a3.x + a3.y);
    }

    // deterministic k_one reduction
#pragma unroll
    for (int j = 0; j < 4; j++) k1buf[dg + j][p] = k1a[j].x + k1a[j].y;
    __syncthreads();
    if (t < Dq) {
        float s = 0.f;
#pragma unroll
        for (int c = 0; c < 16; c++) s += k1buf[t][c];
        g_k1p[sp][bh][t] = s;
    }
}

// ---------------------------------------------------------------------------
// Pass 2: reduce partials.
// ---------------------------------------------------------------------------
__global__ void __launch_bounds__(256)
k2_reduce()
{
    const int bh  = blockIdx.x >> 2;
    const int qtr = blockIdx.x & 3;
    const int base = qtr * (Dq * Dq / 4);
    for (int idx = threadIdx.x; idx < Dq * Dq / 4; idx += 256) {
        float s = 0.f;
#pragma unroll
        for (int p = 0; p < NPART; p++) s += g_part[p][bh][base + idx];
        g_kv[bh][base + idx] = s;
    }
    if (qtr == 0 && threadIdx.x < Dq) {
        float s = 0.f;
#pragma unroll
        for (int p = 0; p < SPLIT1; p++) s += g_k1p[p][bh][threadIdx.x];
        g_k1[bh][threadIdx.x] = s;
    }
}

// ---------------------------------------------------------------------------
// Pass 3: out = phi_q.kv / (phi_q.k_one + 1e-8). FFMA2 packed along d.
// Double-buffered qs, 1 barrier/slab, in-thread normalizer.
// 256 thr = 32 s-thr x 8 e-thr; thread tile 2s x 16e over 64-row slab.
// __launch_bounds__(256,3) for occupancy.
// ---------------------------------------------------------------------------
__global__ void __launch_bounds__(256, 3)
k3_out(const float* __restrict__ Q, const float* __restrict__ mask,
       float* __restrict__ out)
{
    __shared__ float qs[2][SLAB3][68];               // 34.8 KB
    __shared__ __align__(16) u64 kvs2[Dq/2][Dq];     // 16 KB, d-paired kv
    __shared__ __align__(16) u64 k1s2[Dq/2];         // d-paired k_one

    const int t  = threadIdx.x;
    const int bh = blockIdx.x >> 4;
    const int sp = blockIdx.x & 15;
    const int b  = bh >> 4;
    const int s0 = sp * CHUNK3;

    // prologue: build d-paired kv + k_one
    for (int idx = t; idx < Dq * Dq; idx += 256) {
        const int d = idx >> 6, e = idx & 63;
        ((float*)&kvs2[d >> 1][e])[d & 1] = g_kv[bh][idx];
    }
    if (t < Dq / 2) {
        ((float*)&k1s2[t])[0] = g_k1[bh][2 * t];
        ((float*)&k1s2[t])[1] = g_k1[bh][2 * t + 1];
    }

    const float* Qb = Q + (size_t)bh * Sq * Dq;
    const float* Mb = mask + (size_t)b * Sq;
    float*       Ob = out + (size_t)bh * Sq * Dq;

    const int r  = t >> 2;          // staging row 0..63
    const int qt = t & 3;           // staging quarter
    const int e_thr = t & 7;
    const int s_thr = t >> 3;       // rows s_thr, s_thr+32

    float4 qv[4]; float m;

    // prologue: load + stage slab 0
    {
        const int row = s0 + r;
        m = Mb[row];
        const float* Qr = Qb + (size_t)row * Dq + 16 * qt;
#pragma unroll
        for (int c = 0; c < 4; c++) qv[c] = *(const float4*)(Qr + 4 * c);
#pragma unroll
        for (int c = 0; c < 4; c++) {
            *(float4*)&qs[0][r][16 * qt + 4 * c] = make_float4(
                phif(qv[c].x*SCALE)*m, phif(qv[c].y*SCALE)*m,
                phif(qv[c].z*SCALE)*m, phif(qv[c].w*SCALE)*m);
        }
    }

#pragma unroll 1
    for (int sl = 0; sl < NSL3; sl++) {
        __syncthreads();   // qs[sl&1] + (sl==0) kvs2/k1s2 ready; other buf free

        if (sl + 1 < NSL3) {       // issue next slab's gmem loads
            const int row = s0 + (sl + 1) * SLAB3 + r;
            m = Mb[row];
            const float* Qr = Qb + (size_t)row * Dq + 16 * qt;
#pragma unroll
            for (int c = 0; c < 4; c++) qv[c] = *(const float4*)(Qr + 4 * c);
        }

        const int bf = sl & 1;
        u64 acc[2][8];
#pragma unroll
        for (int i = 0; i < 2; i++)
#pragma unroll
            for (int j = 0; j < 8; j++) acc[i][j] = 0ull;
        u64 n2[2] = {0ull, 0ull};

#pragma unroll
        for (int dd = 0; dd < 16; dd++) {
            const ulonglong2 A0 = *(const ulonglong2*)&qs[bf][s_thr][4 * dd];
            const ulonglong2 A1 = *(const ulonglong2*)&qs[bf][s_thr + 32][4 * dd];
            const ulonglong2 k12 = *(const ulonglong2*)&k1s2[2 * dd];
            ulonglong2 B0[4], B1[4];
#pragma unroll
            for (int jj = 0; jj < 4; jj++) {
                B0[jj] = *(const ulonglong2*)&kvs2[2 * dd][2 * e_thr + 16 * jj];
                B1[jj] = *(const ulonglong2*)&kvs2[2 * dd + 1][2 * e_thr + 16 * jj];
            }
#pragma unroll
            for (int jj = 0; jj < 4; jj++) {
                fma2(acc[0][2*jj],   A0.x, B0[jj].x); fma2(acc[0][2*jj+1], A0.x, B0[jj].y);
                fma2(acc[0][2*jj],   A0.y, B1[jj].x); fma2(acc[0][2*jj+1], A0.y, B1[jj].y);
                fma2(acc[1][2*jj],   A1.x, B0[jj].x); fma2(acc[1][2*jj+1], A1.x, B0[jj].y);
                fma2(acc[1][2*jj],   A1.y, B1[jj].x); fma2(acc[1][2*jj+1], A1.y, B1[jj].y);
            }
            fma2(n2[0], A0.x, k12.x); fma2(n2[0], A0.y, k12.y);
            fma2(n2[1], A1.x, k12.x); fma2(n2[1], A1.y, k12.y);
        }

        // epilogue: scale + write
        const int sbase = s0 + sl * SLAB3;
#pragma unroll
        for (int i = 0; i < 2; i++) {
            const int s = s_thr + 32 * i;
            const float2 nv = up2(n2[i]);
            const float inv = 1.0f / (nv.x + nv.y + 1e-8f);
            float* Or = Ob + (size_t)(sbase + s) * Dq;
#pragma unroll
            for (int jj = 0; jj < 4; jj++) {
                const float2 a = up2(acc[i][2*jj]);
                const float2 c = up2(acc[i][2*jj+1]);
                *(float2*)&Or[2 * e_thr + 16 * jj] =
                    make_float2((a.x + a.y) * inv, (c.x + c.y) * inv);
            }
        }

        if (sl + 1 < NSL3) {       // phi + stage next slab
            const int nb = (sl + 1) & 1;
#pragma unroll
            for (int c = 0; c < 4; c++) {
                *(float4*)&qs[nb][r][16 * qt + 4 * c] = make_float4(
                    phif(qv[c].x*SCALE)*m, phif(qv[c].y*SCALE)*m,
                    phif(qv[c].z*SCALE)*m, phif(qv[c].w*SCALE)*m);
            }
        }
    }
}

// ---------------------------------------------------------------------------
extern "C" void kernel_launch(void* const* d_in, const int* in_sizes, int n_in,
                              void* d_out, int out_size)
{
    (void)in_sizes; (void)n_in; (void)out_size;
    const float* Q = (const float*)d_in[0];
    const float* K = (const float*)d_in[1];
    const float* V = (const float*)d_in[2];
    const float* M = (const float*)d_in[3];
    float* O = (float*)d_out;

    k1_partial<<<BHq * SPLIT1, 256>>>(K, V, M);
    k2_reduce <<<BHq * 4,      256>>>();
    k3_out    <<<BHq * SPLIT3, 256>>>(Q, M, O);
}

// round 12
// speedup vs baseline: 1.2136x; 1.2136x over previous
#include <cuda_runtime.h>
#include <cuda_bf16.h>
#include <cstdint>

#define Bq 4
#define Hq 16
#define Sq 4096
#define Dq 64
#define BHq (Bq*Hq)            // 64

#define SPLIT1 16
#define CHUNK1 (Sq/SPLIT1)     // 256 rows per pass-1 block
#define TILE1  32              // rows (16 s-pairs) per staged tile
#define NPART  (SPLIT1*2)

#define SPLIT3 8
#define CHUNK3 (Sq/SPLIT3)     // 512 rows per pass-3 block
#define TILE3  128             // rows per MMA tile
#define NT3    (CHUNK3/TILE3)  // 4

// static scratch (no cudaMalloc allowed)
__device__ float g_part[NPART][BHq][Dq*Dq];
__device__ float g_k1p [SPLIT1][BHq][Dq];
__device__ float g_kvT[BHq][Dq*Dq];   // kv transposed: [e][d]
__device__ float g_k1 [BHq][Dq];

typedef unsigned long long u64;

__device__ __forceinline__ void fma2(u64 &d, u64 a, u64 b) {
    asm("fma.rn.f32x2 %0, %1, %2, %0;" : "+l"(d) : "l"(a), "l"(b));
}
__device__ __forceinline__ float2 up2(u64 v) {
    float2 f;
    asm("mov.b64 {%0, %1}, %2;" : "=f"(f.x), "=f"(f.y) : "l"(v));
    return f;
}
__device__ __forceinline__ float phif(float x) {
    return x > 0.f ? x + 1.f : __expf(x);
}
#define SCALE 0.3535533905932738f  // 1/sqrt(sqrt(64))

// ===================== warp-MMA helpers (sm_80+ ISA) =======================
__device__ __forceinline__ uint32_t s2u(const void* p) {
    uint32_t a;
    asm("{ .reg .u64 t; cvta.to.shared.u64 t, %1; cvt.u32.u64 %0, t; }"
        : "=r"(a) : "l"(p));
    return a;
}
__device__ __forceinline__ void ldsm4(uint32_t r[4], uint32_t addr) {
    asm volatile("ldmatrix.sync.aligned.m8n8.x4.shared.b16 {%0,%1,%2,%3}, [%4];"
                 : "=r"(r[0]), "=r"(r[1]), "=r"(r[2]), "=r"(r[3]) : "r"(addr));
}
__device__ __forceinline__ void mma16816(float c[4], const uint32_t a[4],
                                         uint32_t b0, uint32_t b1) {
    asm volatile(
        "mma.sync.aligned.m16n8k16.row.col.f32.bf16.bf16.f32 "
        "{%0,%1,%2,%3}, {%4,%5,%6,%7}, {%8,%9}, {%0,%1,%2,%3};"
        : "+f"(c[0]), "+f"(c[1]), "+f"(c[2]), "+f"(c[3])
        : "r"(a[0]), "r"(a[1]), "r"(a[2]), "r"(a[3]), "r"(b0), "r"(b1));
}
__device__ __forceinline__ float bhi(float x) {
    return __bfloat162float(__float2bfloat16(x));
}

// ---------------------------------------------------------------------------
// Pass 1 (scalar FFMA2, best measured variant: 87.3us).
// ---------------------------------------------------------------------------
__global__ void __launch_bounds__(256)
k1_partial(const float* __restrict__ K, const float* __restrict__ V,
           const float* __restrict__ mask)
{
    __shared__ __align__(16) float2 ks2[TILE1/2][Dq];
    __shared__ __align__(16) float2 vs2[TILE1/2][Dq];
    __shared__ float k1buf[Dq][17];

    const int t  = threadIdx.x;
    const int bh = blockIdx.x & (BHq - 1);
    const int sp = blockIdx.x >> 6;
    const int b  = bh >> 4;
    const int s0 = sp * CHUNK1;

    const int p  = t >> 4;
    const int dg = (t & 15) << 2;
    const int grp   = t >> 7;
    const int tl    = t & 127;
    const int e_thr = tl & 7;
    const int d0    = (tl >> 3) << 2;

    u64 acc[4][8];
#pragma unroll
    for (int i = 0; i < 4; i++)
#pragma unroll
        for (int j = 0; j < 8; j++) acc[i][j] = 0ull;
    float2 k1a[4] = {{0.f,0.f},{0.f,0.f},{0.f,0.f},{0.f,0.f}};

    const float* Kb = K + (size_t)bh * Sq * Dq;
    const float* Vb = V + (size_t)bh * Sq * Dq;
    const float* Mb = mask + (size_t)b * Sq;

    for (int it = 0; it < CHUNK1 / TILE1; it++) {
        const int sa = s0 + it * TILE1 + 2 * p;
        const float4 ka = *(const float4*)(Kb + (size_t)sa * Dq + dg);
        const float4 kb = *(const float4*)(Kb + (size_t)(sa + 1) * Dq + dg);
        const float4 va = *(const float4*)(Vb + (size_t)sa * Dq + dg);
        const float4 vb = *(const float4*)(Vb + (size_t)(sa + 1) * Dq + dg);
        const float ma  = Mb[sa];
        const float mb2 = Mb[sa + 1];

        float2 P[4];
        P[0] = make_float2(phif(ka.x * SCALE) * ma, phif(kb.x * SCALE) * mb2);
        P[1] = make_float2(phif(ka.y * SCALE) * ma, phif(kb.y * SCALE) * mb2);
        P[2] = make_float2(phif(ka.z * SCALE) * ma, phif(kb.z * SCALE) * mb2);
        P[3] = make_float2(phif(ka.w * SCALE) * ma, phif(kb.w * SCALE) * mb2);

        __syncthreads();
#pragma unroll
        for (int j = 0; j < 4; j++) {
            ks2[p][dg + j] = P[j];
            k1a[j].x += P[j].x; k1a[j].y += P[j].y;
        }
        vs2[p][dg + 0] = make_float2(va.x, vb.x);
        vs2[p][dg + 1] = make_float2(va.y, vb.y);
        vs2[p][dg + 2] = make_float2(va.z, vb.z);
        vs2[p][dg + 3] = make_float2(va.w, vb.w);
        __syncthreads();

#pragma unroll
        for (int s2g = 0; s2g < 8; s2g++) {
            const int s2 = 2 * s2g + grp;
            const ulonglong2 A01 = *(const ulonglong2*)&ks2[s2][d0];
            const ulonglong2 A23 = *(const ulonglong2*)&ks2[s2][d0 + 2];
            u64 B[8];
#pragma unroll
            for (int j = 0; j < 8; j++)
                B[j] = *(const u64*)&vs2[s2][e_thr + 8 * j];
#pragma unroll
            for (int j = 0; j < 8; j++) {
                fma2(acc[0][j], A01.x, B[j]);
                fma2(acc[1][j], A01.y, B[j]);
                fma2(acc[2][j], A23.x, B[j]);
                fma2(acc[3][j], A23.y, B[j]);
            }
        }
    }

    float* dst = &g_part[sp * 2 + grp][bh][0];
#pragma unroll
    for (int i = 0; i < 4; i++)
#pragma unroll
        for (int j = 0; j < 8; j++) {
            const float2 v = up2(acc[i][j]);
            dst[(d0 + i) * Dq + e_thr + 8 * j] = v.x + v.y;
        }

    __syncthreads();
#pragma unroll
    for (int j = 0; j < 4; j++) k1buf[dg + j][p] = k1a[j].x + k1a[j].y;
    __syncthreads();
    if (t < Dq) {
        float s = 0.f;
#pragma unroll
        for (int c = 0; c < 16; c++) s += k1buf[t][c];
        g_k1p[sp][bh][t] = s;
    }
}

// ---------------------------------------------------------------------------
// Pass 2: reduce partials; emit TRANSPOSED kv (kvT[e][d]) + k_one.
// ---------------------------------------------------------------------------
__global__ void __launch_bounds__(256)
k2_reduce()
{
    __shared__ float kvs[Dq][Dq + 1];
    const int bh = blockIdx.x;
    const int t  = threadIdx.x;

    for (int idx = t; idx < Dq * Dq; idx += 256) {
        float s = 0.f;
#pragma unroll
        for (int p = 0; p < NPART; p++) s += g_part[p][bh][idx];
        kvs[idx >> 6][idx & 63] = s;
    }
    if (t < Dq) {
        float s = 0.f;
#pragma unroll
        for (int p = 0; p < SPLIT1; p++) s += g_k1p[p][bh][t];
        g_k1[bh][t] = s;
    }
    __syncthreads();
    for (int idx = t; idx < Dq * Dq; idx += 256) {
        g_kvT[bh][idx] = kvs[idx & 63][idx >> 6];   // kvT[e][d] = kv[d][e]
    }
}

// ---------------------------------------------------------------------------
// Pass 3 (mma.sync bf16 split): out = phi_q.kv / (phi_q.k_one + 1e-8).
// A = phi_q [row-major m x k], B = kvT [n-major] -> mma row.col directly.
// D fp32 = Ah*Bh + Ah*Bl + Al*Bh (lo*lo dropped, ~2^-18 rel).
// 256 thr = 8 warps; warp w owns rows 16w..16w+15 of each 128-row tile.
// ---------------------------------------------------------------------------
#define RS3   72                      // smem row stride in bf16 elems (144 B)
#define SM3_AH 0
#define SM3_AL (SM3_AH + TILE3*RS3*2)       // 18432
#define SM3_BH (SM3_AL + TILE3*RS3*2)       // 36864
#define SM3_BL (SM3_BH + Dq*RS3*2)          // 46080
#define SM3_PN (SM3_BL + Dq*RS3*2)          // 55296: pnorm[128][2] f32
#define SM3_K1 (SM3_PN + TILE3*2*4)         // 56320: k1 f32[64]
#define SM3_SZ (SM3_K1 + 256)               // 56576

__global__ void __launch_bounds__(256)
k3_mma(const float* __restrict__ Q, const float* __restrict__ mask,
       float* __restrict__ out)
{
    extern __shared__ char sm3[];
    const uint32_t sb = s2u(sm3);

    const int t   = threadIdx.x;
    const int w   = t >> 5;
    const int l   = t & 31;
    const int bh  = blockIdx.x >> 3;
    const int sp  = blockIdx.x & 7;
    const int b   = bh >> 4;
    const int s0  = sp * CHUNK3;

    __nv_bfloat16* AH = (__nv_bfloat16*)(sm3 + SM3_AH);
    __nv_bfloat16* AL = (__nv_bfloat16*)(sm3 + SM3_AL);
    __nv_bfloat16* BH = (__nv_bfloat16*)(sm3 + SM3_BH);
    __nv_bfloat16* BL = (__nv_bfloat16*)(sm3 + SM3_BL);
    float*         PN = (float*)(sm3 + SM3_PN);
    float*         K1 = (float*)(sm3 + SM3_K1);

    // ---- stage B (kvT hi/lo bf16, 64 rows) + k1, once per block ----
    // ONLY threads t < 128: r = e row (0..63), hf = d half (0/1).
    if (t < 128) {
        const int r = t >> 1, hf = t & 1;
        const float* src = &g_kvT[bh][r * 64 + hf * 32];
        __nv_bfloat16* dh = BH + r * RS3 + hf * 32;
        __nv_bfloat16* dl = BL + r * RS3 + hf * 32;
#pragma unroll
        for (int c = 0; c < 8; c++) {
            const float4 v = *(const float4*)(src + 4 * c);
            const float h0 = bhi(v.x), h1 = bhi(v.y), h2 = bhi(v.z), h3 = bhi(v.w);
            dh[4*c+0] = __float2bfloat16(h0); dh[4*c+1] = __float2bfloat16(h1);
            dh[4*c+2] = __float2bfloat16(h2); dh[4*c+3] = __float2bfloat16(h3);
            dl[4*c+0] = __float2bfloat16(v.x - h0); dl[4*c+1] = __float2bfloat16(v.y - h1);
            dl[4*c+2] = __float2bfloat16(v.z - h2); dl[4*c+3] = __float2bfloat16(v.w - h3);
        }
    }
    if (t < Dq) K1[t] = g_k1[bh][t];

    const float* Qb = Q + (size_t)bh * Sq * Dq;
    const float* Mb = mask + (size_t)b * Sq;
    float*       Ob = out + (size_t)bh * Sq * Dq;

    // ldmatrix lane addressing (constant per thread)
    // A: row = 16w + (l&15), col-byte = ((l>>4)&1)*16 + 32*kk
    const uint32_t aRow = 16 * w + (l & 15);
    const uint32_t aCol = ((l >> 4) & 1) * 16;
    // B: row = 16*ntp + (l&7) + ((l&16)?8:0), col-byte = ((l>>3)&1)*16 + 32*kk
    const uint32_t bRow = (l & 7) + ((l & 16) >> 1);
    const uint32_t bCol = ((l >> 3) & 1) * 16;

#pragma unroll 1
    for (int it = 0; it < NT3; it++) {
        const int sbase = s0 + it * TILE3;

        __syncthreads();   // previous tile's PN reads complete; smem A free

        // ---- stage A tile (phi_q hi/lo) + norm partials ----
        {
            const int r = t >> 1, hf = t & 1;
            const int row = sbase + r;
            const float m = Mb[row];
            const float* Qr = Qb + (size_t)row * Dq + hf * 32;
            __nv_bfloat16* dh = AH + r * RS3 + hf * 32;
            __nv_bfloat16* dl = AL + r * RS3 + hf * 32;
            float ns = 0.f;
#pragma unroll
            for (int c = 0; c < 8; c++) {
                const float4 q = *(const float4*)(Qr + 4 * c);
                const float p0 = phif(q.x * SCALE) * m;
                const float p1 = phif(q.y * SCALE) * m;
                const float p2 = phif(q.z * SCALE) * m;
                const float p3 = phif(q.w * SCALE) * m;
                const float h0 = bhi(p0), h1 = bhi(p1), h2 = bhi(p2), h3 = bhi(p3);
                dh[4*c+0] = __float2bfloat16(h0); dh[4*c+1] = __float2bfloat16(h1);
                dh[4*c+2] = __float2bfloat16(h2); dh[4*c+3] = __float2bfloat16(h3);
                dl[4*c+0] = __float2bfloat16(p0 - h0); dl[4*c+1] = __float2bfloat16(p1 - h1);
                dl[4*c+2] = __float2bfloat16(p2 - h2); dl[4*c+3] = __float2bfloat16(p3 - h3);
                const float* kc = K1 + hf * 32 + 4 * c;
                ns += p0 * kc[0] + p1 * kc[1] + p2 * kc[2] + p3 * kc[3];
            }
            PN[r * 2 + hf] = ns;
        }
        __syncthreads();   // A, B(it==0), PN visible

        // ---- MMA mainloop: 4 k-steps x 4 n-tiles x 3 split terms ----
        float c[8][4];
#pragma unroll
        for (int j = 0; j < 8; j++)
#pragma unroll
            for (int i = 0; i < 4; i++) c[j][i] = 0.f;

#pragma unroll
        for (int kk = 0; kk < 4; kk++) {
            uint32_t ah[4], al[4];
            ldsm4(ah, sb + SM3_AH + aRow * (RS3*2) + aCol + 32 * kk);
            ldsm4(al, sb + SM3_AL + aRow * (RS3*2) + aCol + 32 * kk);
#pragma unroll
            for (int ntp = 0; ntp < 4; ntp++) {
                uint32_t bhv[4], blv[4];
                const uint32_t brow = 16 * ntp + bRow;
                ldsm4(bhv, sb + SM3_BH + brow * (RS3*2) + bCol + 32 * kk);
                ldsm4(blv, sb + SM3_BL + brow * (RS3*2) + bCol + 32 * kk);
                mma16816(c[2*ntp],   ah, bhv[0], bhv[1]);
                mma16816(c[2*ntp],   ah, blv[0], blv[1]);
                mma16816(c[2*ntp],   al, bhv[0], bhv[1]);
                mma16816(c[2*ntp+1], ah, bhv[2], bhv[3]);
                mma16816(c[2*ntp+1], ah, blv[2], blv[3]);
                mma16816(c[2*ntp+1], al, bhv[2], bhv[3]);
            }
        }

        // ---- epilogue: normalize + store ----
        {
            const int r0 = 16 * w + (l >> 2);
            const int r1 = r0 + 8;
            const float inv0 = 1.0f / (PN[r0 * 2] + PN[r0 * 2 + 1] + 1e-8f);
            const float inv1 = 1.0f / (PN[r1 * 2] + PN[r1 * 2 + 1] + 1e-8f);
            float* O0 = Ob + (size_t)(sbase + r0) * Dq + 2 * (l & 3);
            float* O1 = Ob + (size_t)(sbase + r1) * Dq + 2 * (l & 3);
#pragma unroll
            for (int j = 0; j < 8; j++) {
                *(float2*)(O0 + 8 * j) = make_float2(c[j][0] * inv0, c[j][1] * inv0);
                *(float2*)(O1 + 8 * j) = make_float2(c[j][2] * inv1, c[j][3] * inv1);
            }
        }
    }
}

// ---------------------------------------------------------------------------
extern "C" void kernel_launch(void* const* d_in, const int* in_sizes, int n_in,
                              void* d_out, int out_size)
{
    (void)in_sizes; (void)n_in; (void)out_size;
    const float* Q = (const float*)d_in[0];
    const float* K = (const float*)d_in[1];
    const float* V = (const float*)d_in[2];
    const float* M = (const float*)d_in[3];
    float* O = (float*)d_out;

    cudaFuncSetAttribute(k3_mma, cudaFuncAttributeMaxDynamicSharedMemorySize, SM3_SZ);

    k1_partial<<<BHq * SPLIT1, 256>>>(K, V, M);
    k2_reduce <<<BHq,          256>>>();
    k3_mma    <<<BHq * SPLIT3, 256, SM3_SZ>>>(Q, M, O);
}

// round 13
// speedup vs baseline: 1.7999x; 1.4832x over previous
#include <cuda_runtime.h>
#include <cuda_bf16.h>
#include <cstdint>

#define Bq 4
#define Hq 16
#define Sq 4096
#define Dq 64
#define BHq (Bq*Hq)            // 64

#define SPLIT1 8
#define CHUNK1 (Sq/SPLIT1)     // 512 s-rows per pass-1 block
#define NT1    8               // tiles of 64 s
#define NPART  SPLIT1

#define SPLIT3 8
#define CHUNK3 (Sq/SPLIT3)     // 512 rows per pass-3 block
#define TILE3  128
#define NT3    (CHUNK3/TILE3)  // 4

__device__ float g_part[NPART][BHq][Dq*Dq];
__device__ float g_k1p [SPLIT1][BHq][Dq];
__device__ float g_kvT[BHq][Dq*Dq];   // kv transposed: [e][d]
__device__ float g_k1 [BHq][Dq];

__device__ __forceinline__ float phif(float x) {
    return x > 0.f ? x + 1.f : __expf(x);
}
#define SCALE 0.3535533905932738f  // 1/sqrt(sqrt(64))

__device__ __forceinline__ uint32_t s2u(const void* p) {
    uint32_t a;
    asm("{ .reg .u64 t; cvta.to.shared.u64 t, %1; cvt.u32.u64 %0, t; }"
        : "=r"(a) : "l"(p));
    return a;
}
__device__ __forceinline__ void ldsm4(uint32_t r[4], uint32_t addr) {
    asm volatile("ldmatrix.sync.aligned.m8n8.x4.shared.b16 {%0,%1,%2,%3}, [%4];"
                 : "=r"(r[0]), "=r"(r[1]), "=r"(r[2]), "=r"(r[3]) : "r"(addr));
}
__device__ __forceinline__ void mma_tf32(float c[4], const uint32_t a[4],
                                         uint32_t b0, uint32_t b1) {
    asm volatile(
        "mma.sync.aligned.m16n8k8.row.col.f32.tf32.tf32.f32 "
        "{%0,%1,%2,%3}, {%4,%5,%6,%7}, {%8,%9}, {%0,%1,%2,%3};"
        : "+f"(c[0]), "+f"(c[1]), "+f"(c[2]), "+f"(c[3])
        : "r"(a[0]), "r"(a[1]), "r"(a[2]), "r"(a[3]), "r"(b0), "r"(b1));
}
__device__ __forceinline__ uint32_t f2tf(float x) {
    uint32_t r;
    asm("cvt.rna.tf32.f32 %0, %1;" : "=r"(r) : "f"(x));
    return r;
}

// All smem tiles: row stride 68 u32 words (272 B: 272%128==16 -> ldsm rows
// conflict-free). 16B-chunk index XOR'd with (row>>3)&1 at store; ldsm
// lane addresses apply the matching XOR (derivation verified per group).

// ---------------------------------------------------------------------------
// Pass 1 (tf32 MMA): kv[d][e] = sum_s phi_k[s][d] v[s][e].
// Staging writes TRANSPOSED tf32 tiles kT[d][s], vT[e][s] (64x64, swizzled).
// 8 warps: warp w -> m-tile (d) = w>>1 (16 rows), n-half (e) = w&1 (32 cols).
// 8 k-steps (k8) per 64-s tile, 8 tiles.
// ---------------------------------------------------------------------------
__global__ void __launch_bounds__(256)
k1_mma(const float* __restrict__ K, const float* __restrict__ V,
       const float* __restrict__ mask)
{
    __shared__ uint32_t kT[64*68];
    __shared__ uint32_t vT[64*68];
    __shared__ float k1b[8][68];

    const int t  = threadIdx.x;
    const int w  = t >> 5, l = t & 31;
    const int bh = blockIdx.x & (BHq - 1);
    const int sp = blockIdx.x >> 6;
    const int b  = bh >> 4;
    const int s0 = sp * CHUNK1;

    const int r  = t >> 2;          // staged s-row in tile (0..63)
    const int qc = t & 3;           // d-block (16 elems)

    const int mt = w >> 1, nh = w & 1;
    const uint32_t uKT = s2u(kT), uVT = s2u(vT);
    // ldsm addressing with swizzle-compensated 16B selector
    const uint32_t aRow  = 16 * mt + (l & 15);
    const uint32_t selA  = ((l >> 4) & 1) ^ ((l >> 3) & 1);
    const uint32_t aBase = uKT + aRow * 272 + selA * 16;
    const uint32_t bRow  = 32 * nh + (l & 7) + 8 * ((l >> 4) & 1);
    const uint32_t selB  = ((l >> 3) & 1) ^ ((l >> 4) & 1);
    const uint32_t bBase = uVT + bRow * 272 + selB * 16;

    float c[4][4];
#pragma unroll
    for (int i = 0; i < 4; i++)
#pragma unroll
        for (int j = 0; j < 4; j++) c[i][j] = 0.f;
    float k1loc[16];
#pragma unroll
    for (int i = 0; i < 16; i++) k1loc[i] = 0.f;

    const float* Kb = K + (size_t)bh * Sq * Dq;
    const float* Vb = V + (size_t)bh * Sq * Dq;
    const float* Mb = mask + (size_t)b * Sq;

#pragma unroll 1
    for (int it = 0; it < NT1; it++) {
        const int s = s0 + it * 64 + r;
        float4 kk4[4], vv4[4];
#pragma unroll
        for (int c4 = 0; c4 < 4; c4++) {
            kk4[c4] = *(const float4*)(Kb + (size_t)s * Dq + 16 * qc + 4 * c4);
            vv4[c4] = *(const float4*)(Vb + (size_t)s * Dq + 16 * qc + 4 * c4);
        }
        const float m = Mb[s];

        __syncthreads();   // previous tile's ldsm reads complete

        // transposed swizzled stores: element d -> row d, s-word r
#pragma unroll
        for (int c4 = 0; c4 < 4; c4++) {
            const float kv_[4] = {kk4[c4].x, kk4[c4].y, kk4[c4].z, kk4[c4].w};
            const float vv_[4] = {vv4[c4].x, vv4[c4].y, vv4[c4].z, vv4[c4].w};
#pragma unroll
            for (int j = 0; j < 4; j++) {
                const int d  = 16 * qc + 4 * c4 + j;
                const int xr = ((4 * c4 + j) >> 3) & 1;   // = (d>>3)&1
                const int wd = d * 68 + ((((r >> 2) ^ xr) << 2) | (r & 3));
                const float p = phif(kv_[j] * SCALE) * m;
                k1loc[4 * c4 + j] += p;
                kT[wd] = f2tf(p);
                vT[wd] = f2tf(vv_[j]);
            }
        }
        __syncthreads();

#pragma unroll
        for (int kk = 0; kk < 8; kk++) {
            uint32_t a[4];
            ldsm4(a, aBase + kk * 32);
#pragma unroll
            for (int np = 0; np < 2; np++) {
                uint32_t bb[4];
                ldsm4(bb, bBase + np * 16 * 272 + kk * 32);
                mma_tf32(c[2*np],   a, bb[0], bb[1]);
                mma_tf32(c[2*np+1], a, bb[2], bb[3]);
            }
        }
    }

    // epilogue: kv partial
    float* dst = &g_part[sp][bh][0];
    const int r0 = 16 * mt + (l >> 2), r1 = r0 + 8;
#pragma unroll
    for (int nt = 0; nt < 4; nt++) {
        const int e = 32 * nh + 8 * nt + 2 * (l & 3);
        *(float2*)&dst[r0 * 64 + e] = make_float2(c[nt][0], c[nt][1]);
        *(float2*)&dst[r1 * 64 + e] = make_float2(c[nt][2], c[nt][3]);
    }

    // deterministic k_one reduction: warp xor-reduce over same-qc lanes
#pragma unroll
    for (int ofs = 4; ofs <= 16; ofs <<= 1)
#pragma unroll
        for (int i = 0; i < 16; i++)
            k1loc[i] += __shfl_xor_sync(0xffffffffu, k1loc[i], ofs);
    if (l < 4) {
#pragma unroll
        for (int i = 0; i < 16; i++) k1b[w][16 * l + i] = k1loc[i];
    }
    __syncthreads();
    if (t < Dq) {
        float s = 0.f;
#pragma unroll
        for (int ww = 0; ww < 8; ww++) s += k1b[ww][t];
        g_k1p[sp][bh][t] = s;
    }
}

// ---------------------------------------------------------------------------
// Pass 2: reduce partials; emit kvT[e][d] + k_one.
// ---------------------------------------------------------------------------
__global__ void __launch_bounds__(256)
k2_reduce()
{
    __shared__ float kvs[Dq][Dq + 1];
    const int bh = blockIdx.x;
    const int t  = threadIdx.x;

    for (int idx = t; idx < Dq * Dq; idx += 256) {
        float s = 0.f;
#pragma unroll
        for (int p = 0; p < NPART; p++) s += g_part[p][bh][idx];
        kvs[idx >> 6][idx & 63] = s;
    }
    if (t < Dq) {
        float s = 0.f;
#pragma unroll
        for (int p = 0; p < SPLIT1; p++) s += g_k1p[p][bh][t];
        g_k1[bh][t] = s;
    }
    __syncthreads();
    for (int idx = t; idx < Dq * Dq; idx += 256) {
        g_kvT[bh][idx] = kvs[idx & 63][idx >> 6];
    }
}

// ---------------------------------------------------------------------------
// Pass 3 (tf32 MMA): out = phi_q.kv / (phi_q.k_one + 1e-8).
// A = phi_q [s][d] row-major (natural), B = kvT [e][d] n-major (natural).
// Single tf32 term. 8 warps, warp w = m-tile (16 rows), full n=64.
// ---------------------------------------------------------------------------
#define SM3_A  0
#define SM3_B  (SM3_A + TILE3*68*4)         // 34816
#define SM3_PN (SM3_B + Dq*68*4)            // 52224: pnorm[128][2] f32
#define SM3_K1 (SM3_PN + TILE3*2*4)         // 53248
#define SM3_SZ (SM3_K1 + 256)               // 53504

__global__ void __launch_bounds__(256)
k3_mma(const float* __restrict__ Q, const float* __restrict__ mask,
       float* __restrict__ out)
{
    extern __shared__ char sm3[];
    const uint32_t sb = s2u(sm3);

    const int t  = threadIdx.x;
    const int w  = t >> 5, l = t & 31;
    const int bh = blockIdx.x >> 3;
    const int sp = blockIdx.x & 7;
    const int b  = bh >> 4;
    const int s0 = sp * CHUNK3;

    uint32_t* A = (uint32_t*)(sm3 + SM3_A);
    uint32_t* Bm = (uint32_t*)(sm3 + SM3_B);
    float* PN = (float*)(sm3 + SM3_PN);
    float* K1 = (float*)(sm3 + SM3_K1);

    // ---- stage B (kvT tf32, swizzled) + k1, once per block ----
    if (t < 128) {
        const int r = t >> 1, hf = t & 1;   // e row, d half
        const float* src = &g_kvT[bh][r * 64 + hf * 32];
        const int xr = (r >> 3) & 1;
#pragma unroll
        for (int cc = 0; cc < 8; cc++) {
            const float4 v = *(const float4*)(src + 4 * cc);
            const int chunk = (8 * hf + cc) ^ xr;
            *(uint4*)&Bm[r * 68 + 4 * chunk] =
                make_uint4(f2tf(v.x), f2tf(v.y), f2tf(v.z), f2tf(v.w));
        }
    }
    if (t < Dq) K1[t] = g_k1[bh][t];

    const float* Qb = Q + (size_t)bh * Sq * Dq;
    const float* Mb = mask + (size_t)b * Sq;
    float*       Ob = out + (size_t)bh * Sq * Dq;

    const uint32_t aRow  = 16 * w + (l & 15);
    const uint32_t selA  = ((l >> 4) & 1) ^ ((l >> 3) & 1);
    const uint32_t aBase = sb + SM3_A + aRow * 272 + selA * 16;
    const uint32_t bRow  = (l & 7) + 8 * ((l >> 4) & 1);
    const uint32_t selB  = ((l >> 3) & 1) ^ ((l >> 4) & 1);
    const uint32_t bBase = sb + SM3_B + bRow * 272 + selB * 16;

#pragma unroll 1
    for (int it = 0; it < NT3; it++) {
        const int sbase = s0 + it * TILE3;

        __syncthreads();   // previous tile's reads complete

        // ---- stage A tile (phi_q tf32, swizzled) + norm partials ----
        {
            const int r = t >> 1, hf = t & 1;
            const int row = sbase + r;
            const float m = Mb[row];
            const float* Qr = Qb + (size_t)row * Dq + hf * 32;
            const int xr = (r >> 3) & 1;
            float ns = 0.f;
#pragma unroll
            for (int cc = 0; cc < 8; cc++) {
                const float4 q = *(const float4*)(Qr + 4 * cc);
                const float p0 = phif(q.x * SCALE) * m;
                const float p1 = phif(q.y * SCALE) * m;
                const float p2 = phif(q.z * SCALE) * m;
                const float p3 = phif(q.w * SCALE) * m;
                const int chunk = (8 * hf + cc) ^ xr;
                *(uint4*)&A[r * 68 + 4 * chunk] =
                    make_uint4(f2tf(p0), f2tf(p1), f2tf(p2), f2tf(p3));
                const float* kc = K1 + hf * 32 + 4 * cc;
                ns += p0 * kc[0] + p1 * kc[1] + p2 * kc[2] + p3 * kc[3];
            }
            PN[r * 2 + hf] = ns;
        }
        __syncthreads();

        // ---- MMA mainloop: 8 k-steps x 8 n8-tiles, single tf32 term ----
        float c[8][4];
#pragma unroll
        for (int j = 0; j < 8; j++)
#pragma unroll
            for (int i = 0; i < 4; i++) c[j][i] = 0.f;

#pragma unroll
        for (int kk = 0; kk < 8; kk++) {
            uint32_t a[4];
            ldsm4(a, aBase + kk * 32);
#pragma unroll
            for (int ntp = 0; ntp < 4; ntp++) {
                uint32_t bb[4];
                ldsm4(bb, bBase + ntp * 16 * 272 + kk * 32);
                mma_tf32(c[2*ntp],   a, bb[0], bb[1]);
                mma_tf32(c[2*ntp+1], a, bb[2], bb[3]);
            }
        }

        // ---- epilogue: normalize + store ----
        {
            const int r0 = 16 * w + (l >> 2);
            const int r1 = r0 + 8;
            const float inv0 = 1.0f / (PN[r0 * 2] + PN[r0 * 2 + 1] + 1e-8f);
            const float inv1 = 1.0f / (PN[r1 * 2] + PN[r1 * 2 + 1] + 1e-8f);
            float* O0 = Ob + (size_t)(sbase + r0) * Dq + 2 * (l & 3);
            float* O1 = Ob + (size_t)(sbase + r1) * Dq + 2 * (l & 3);
#pragma unroll
            for (int j = 0; j < 8; j++) {
                *(float2*)(O0 + 8 * j) = make_float2(c[j][0] * inv0, c[j][1] * inv0);
                *(float2*)(O1 + 8 * j) = make_float2(c[j][2] * inv1, c[j][3] * inv1);
            }
        }
    }
}

// ---------------------------------------------------------------------------
extern "C" void kernel_launch(void* const* d_in, const int* in_sizes, int n_in,
                              void* d_out, int out_size)
{
    (void)in_sizes; (void)n_in; (void)out_size;
    const float* Q = (const float*)d_in[0];
    const float* K = (const float*)d_in[1];
    const float* V = (const float*)d_in[2];
    const float* M = (const float*)d_in[3];
    float* O = (float*)d_out;

    cudaFuncSetAttribute(k3_mma, cudaFuncAttributeMaxDynamicSharedMemorySize, SM3_SZ);

    k1_mma   <<<BHq * SPLIT1, 256>>>(K, V, M);
    k2_reduce<<<BHq,          256>>>();
    k3_mma   <<<BHq * SPLIT3, 256, SM3_SZ>>>(Q, M, O);
}

// round 14
// speedup vs baseline: 1.8042x; 1.0023x over previous
#include <cuda_runtime.h>
#include <cuda_bf16.h>
#include <cstdint>

#define Bq 4
#define Hq 16
#define Sq 4096
#define Dq 64
#define BHq (Bq*Hq)            // 64

#define SPLIT1 8
#define CHUNK1 (Sq/SPLIT1)     // 512 s-rows per pass-1 block
#define NT1    8               // tiles of 64 s
#define NPART  SPLIT1

#define SPLIT3 8
#define CHUNK3 (Sq/SPLIT3)     // 512 rows per pass-3 block
#define TILE3  128
#define NT3    (CHUNK3/TILE3)  // 4

__device__ float g_part[NPART][BHq][Dq*Dq];
__device__ float g_k1p [SPLIT1][BHq][Dq];
__device__ float g_kvT[BHq][Dq*Dq];   // kv transposed: [e][d]
__device__ float g_k1 [BHq][Dq];

__device__ __forceinline__ float phif(float x) {
    return x > 0.f ? x + 1.f : __expf(x);
}
#define SCALE 0.3535533905932738f  // 1/sqrt(sqrt(64))

__device__ __forceinline__ uint32_t s2u(const void* p) {
    uint32_t a;
    asm("{ .reg .u64 t; cvta.to.shared.u64 t, %1; cvt.u32.u64 %0, t; }"
        : "=r"(a) : "l"(p));
    return a;
}
__device__ __forceinline__ void ldsm4(uint32_t r[4], uint32_t addr) {
    asm volatile("ldmatrix.sync.aligned.m8n8.x4.shared.b16 {%0,%1,%2,%3}, [%4];"
                 : "=r"(r[0]), "=r"(r[1]), "=r"(r[2]), "=r"(r[3]) : "r"(addr));
}
__device__ __forceinline__ void mma_tf32(float c[4], const uint32_t a[4],
                                         uint32_t b0, uint32_t b1) {
    asm volatile(
        "mma.sync.aligned.m16n8k8.row.col.f32.tf32.tf32.f32 "
        "{%0,%1,%2,%3}, {%4,%5,%6,%7}, {%8,%9}, {%0,%1,%2,%3};"
        : "+f"(c[0]), "+f"(c[1]), "+f"(c[2]), "+f"(c[3])
        : "r"(a[0]), "r"(a[1]), "r"(a[2]), "r"(a[3]), "r"(b0), "r"(b1));
}
__device__ __forceinline__ uint32_t f2tf(float x) {
    uint32_t r;
    asm("cvt.rna.tf32.f32 %0, %1;" : "=r"(r) : "f"(x));
    return r;
}

// All smem tiles: row stride 68 u32 words (272 B: 272%128==16 -> ldsm rows
// conflict-free). 16B-chunk index XOR'd with (row>>3)&1 at store; ldsm
// lane addresses apply the matching XOR (derivation verified per group).

// ---------------------------------------------------------------------------
// Pass 1 (tf32 MMA): kv[d][e] = sum_s phi_k[s][d] v[s][e].
// Staging writes TRANSPOSED tf32 tiles kT[d][s], vT[e][s] (64x64, swizzled).
// 8 warps: warp w -> m-tile (d) = w>>1 (16 rows), n-half (e) = w&1 (32 cols).
// 8 k-steps (k8) per 64-s tile, 8 tiles.
// ---------------------------------------------------------------------------
__global__ void __launch_bounds__(256)
k1_mma(const float* __restrict__ K, const float* __restrict__ V,
       const float* __restrict__ mask)
{
    __shared__ uint32_t kT[64*68];
    __shared__ uint32_t vT[64*68];
    __shared__ float k1b[8][68];

    const int t  = threadIdx.x;
    const int w  = t >> 5, l = t & 31;
    const int bh = blockIdx.x & (BHq - 1);
    const int sp = blockIdx.x >> 6;
    const int b  = bh >> 4;
    const int s0 = sp * CHUNK1;

    const int r  = t >> 2;          // staged s-row in tile (0..63)
    const int qc = t & 3;           // d-block (16 elems)

    const int mt = w >> 1, nh = w & 1;
    const uint32_t uKT = s2u(kT), uVT = s2u(vT);
    // ldsm addressing with swizzle-compensated 16B selector
    const uint32_t aRow  = 16 * mt + (l & 15);
    const uint32_t selA  = ((l >> 4) & 1) ^ ((l >> 3) & 1);
    const uint32_t aBase = uKT + aRow * 272 + selA * 16;
    const uint32_t bRow  = 32 * nh + (l & 7) + 8 * ((l >> 4) & 1);
    const uint32_t selB  = ((l >> 3) & 1) ^ ((l >> 4) & 1);
    const uint32_t bBase = uVT + bRow * 272 + selB * 16;

    float c[4][4];
#pragma unroll
    for (int i = 0; i < 4; i++)
#pragma unroll
        for (int j = 0; j < 4; j++) c[i][j] = 0.f;
    float k1loc[16];
#pragma unroll
    for (int i = 0; i < 16; i++) k1loc[i] = 0.f;

    const float* Kb = K + (size_t)bh * Sq * Dq;
    const float* Vb = V + (size_t)bh * Sq * Dq;
    const float* Mb = mask + (size_t)b * Sq;

#pragma unroll 1
    for (int it = 0; it < NT1; it++) {
        const int s = s0 + it * 64 + r;
        float4 kk4[4], vv4[4];
#pragma unroll
        for (int c4 = 0; c4 < 4; c4++) {
            kk4[c4] = *(const float4*)(Kb + (size_t)s * Dq + 16 * qc + 4 * c4);
            vv4[c4] = *(const float4*)(Vb + (size_t)s * Dq + 16 * qc + 4 * c4);
        }
        const float m = Mb[s];

        __syncthreads();   // previous tile's ldsm reads complete

        // transposed swizzled stores: element d -> row d, s-word r
#pragma unroll
        for (int c4 = 0; c4 < 4; c4++) {
            const float kv_[4] = {kk4[c4].x, kk4[c4].y, kk4[c4].z, kk4[c4].w};
            const float vv_[4] = {vv4[c4].x, vv4[c4].y, vv4[c4].z, vv4[c4].w};
#pragma unroll
            for (int j = 0; j < 4; j++) {
                const int d  = 16 * qc + 4 * c4 + j;
                const int xr = ((4 * c4 + j) >> 3) & 1;   // = (d>>3)&1
                const int wd = d * 68 + ((((r >> 2) ^ xr) << 2) | (r & 3));
                const float p = phif(kv_[j] * SCALE) * m;
                k1loc[4 * c4 + j] += p;
                kT[wd] = f2tf(p);
                vT[wd] = f2tf(vv_[j]);
            }
        }
        __syncthreads();

#pragma unroll
        for (int kk = 0; kk < 8; kk++) {
            uint32_t a[4];
            ldsm4(a, aBase + kk * 32);
#pragma unroll
            for (int np = 0; np < 2; np++) {
                uint32_t bb[4];
                ldsm4(bb, bBase + np * 16 * 272 + kk * 32);
                mma_tf32(c[2*np],   a, bb[0], bb[1]);
                mma_tf32(c[2*np+1], a, bb[2], bb[3]);
            }
        }
    }

    // epilogue: kv partial
    float* dst = &g_part[sp][bh][0];
    const int r0 = 16 * mt + (l >> 2), r1 = r0 + 8;
#pragma unroll
    for (int nt = 0; nt < 4; nt++) {
        const int e = 32 * nh + 8 * nt + 2 * (l & 3);
        *(float2*)&dst[r0 * 64 + e] = make_float2(c[nt][0], c[nt][1]);
        *(float2*)&dst[r1 * 64 + e] = make_float2(c[nt][2], c[nt][3]);
    }

    // deterministic k_one reduction: warp xor-reduce over same-qc lanes
#pragma unroll
    for (int ofs = 4; ofs <= 16; ofs <<= 1)
#pragma unroll
        for (int i = 0; i < 16; i++)
            k1loc[i] += __shfl_xor_sync(0xffffffffu, k1loc[i], ofs);
    if (l < 4) {
#pragma unroll
        for (int i = 0; i < 16; i++) k1b[w][16 * l + i] = k1loc[i];
    }
    __syncthreads();
    if (t < Dq) {
        float s = 0.f;
#pragma unroll
        for (int ww = 0; ww < 8; ww++) s += k1b[ww][t];
        g_k1p[sp][bh][t] = s;
    }
}

// ---------------------------------------------------------------------------
// Pass 2: reduce partials; emit kvT[e][d] + k_one.
// ---------------------------------------------------------------------------
__global__ void __launch_bounds__(256)
k2_reduce()
{
    __shared__ float kvs[Dq][Dq + 1];
    const int bh = blockIdx.x;
    const int t  = threadIdx.x;

    for (int idx = t; idx < Dq * Dq; idx += 256) {
        float s = 0.f;
#pragma unroll
        for (int p = 0; p < NPART; p++) s += g_part[p][bh][idx];
        kvs[idx >> 6][idx & 63] = s;
    }
    if (t < Dq) {
        float s = 0.f;
#pragma unroll
        for (int p = 0; p < SPLIT1; p++) s += g_k1p[p][bh][t];
        g_k1[bh][t] = s;
    }
    __syncthreads();
    for (int idx = t; idx < Dq * Dq; idx += 256) {
        g_kvT[bh][idx] = kvs[idx & 63][idx >> 6];
    }
}

// ---------------------------------------------------------------------------
// Pass 3 (tf32 MMA): out = phi_q.kv / (phi_q.k_one + 1e-8).
// A = phi_q [s][d] row-major (natural), B = kvT [e][d] n-major (natural).
// Single tf32 term. 8 warps, warp w = m-tile (16 rows), full n=64.
// ---------------------------------------------------------------------------
#define SM3_A  0
#define SM3_B  (SM3_A + TILE3*68*4)         // 34816
#define SM3_PN (SM3_B + Dq*68*4)            // 52224: pnorm[128][2] f32
#define SM3_K1 (SM3_PN + TILE3*2*4)         // 53248
#define SM3_SZ (SM3_K1 + 256)               // 53504

__global__ void __launch_bounds__(256)
k3_mma(const float* __restrict__ Q, const float* __restrict__ mask,
       float* __restrict__ out)
{
    extern __shared__ char sm3[];
    const uint32_t sb = s2u(sm3);

    const int t  = threadIdx.x;
    const int w  = t >> 5, l = t & 31;
    const int bh = blockIdx.x >> 3;
    const int sp = blockIdx.x & 7;
    const int b  = bh >> 4;
    const int s0 = sp * CHUNK3;

    uint32_t* A = (uint32_t*)(sm3 + SM3_A);
    uint32_t* Bm = (uint32_t*)(sm3 + SM3_B);
    float* PN = (float*)(sm3 + SM3_PN);
    float* K1 = (float*)(sm3 + SM3_K1);

    // ---- stage B (kvT tf32, swizzled) + k1, once per block ----
    if (t < 128) {
        const int r = t >> 1, hf = t & 1;   // e row, d half
        const float* src = &g_kvT[bh][r * 64 + hf * 32];
        const int xr = (r >> 3) & 1;
#pragma unroll
        for (int cc = 0; cc < 8; cc++) {
            const float4 v = *(const float4*)(src + 4 * cc);
            const int chunk = (8 * hf + cc) ^ xr;
            *(uint4*)&Bm[r * 68 + 4 * chunk] =
                make_uint4(f2tf(v.x), f2tf(v.y), f2tf(v.z), f2tf(v.w));
        }
    }
    if (t < Dq) K1[t] = g_k1[bh][t];

    const float* Qb = Q + (size_t)bh * Sq * Dq;
    const float* Mb = mask + (size_t)b * Sq;
    float*       Ob = out + (size_t)bh * Sq * Dq;

    const uint32_t aRow  = 16 * w + (l & 15);
    const uint32_t selA  = ((l >> 4) & 1) ^ ((l >> 3) & 1);
    const uint32_t aBase = sb + SM3_A + aRow * 272 + selA * 16;
    const uint32_t bRow  = (l & 7) + 8 * ((l >> 4) & 1);
    const uint32_t selB  = ((l >> 3) & 1) ^ ((l >> 4) & 1);
    const uint32_t bBase = sb + SM3_B + bRow * 272 + selB * 16;

#pragma unroll 1
    for (int it = 0; it < NT3; it++) {
        const int sbase = s0 + it * TILE3;

        __syncthreads();   // previous tile's reads complete

        // ---- stage A tile (phi_q tf32, swizzled) + norm partials ----
        {
            const int r = t >> 1, hf = t & 1;
            const int row = sbase + r;
            const float m = Mb[row];
            const float* Qr = Qb + (size_t)row * Dq + hf * 32;
            const int xr = (r >> 3) & 1;
            float ns = 0.f;
#pragma unroll
            for (int cc = 0; cc < 8; cc++) {
                const float4 q = *(const float4*)(Qr + 4 * cc);
                const float p0 = phif(q.x * SCALE) * m;
                const float p1 = phif(q.y * SCALE) * m;
                const float p2 = phif(q.z * SCALE) * m;
                const float p3 = phif(q.w * SCALE) * m;
                const int chunk = (8 * hf + cc) ^ xr;
                *(uint4*)&A[r * 68 + 4 * chunk] =
                    make_uint4(f2tf(p0), f2tf(p1), f2tf(p2), f2tf(p3));
                const float* kc = K1 + hf * 32 + 4 * cc;
                ns += p0 * kc[0] + p1 * kc[1] + p2 * kc[2] + p3 * kc[3];
            }
            PN[r * 2 + hf] = ns;
        }
        __syncthreads();

        // ---- MMA mainloop: 8 k-steps x 8 n8-tiles, single tf32 term ----
        float c[8][4];
#pragma unroll
        for (int j = 0; j < 8; j++)
#pragma unroll
            for (int i = 0; i < 4; i++) c[j][i] = 0.f;

#pragma unroll
        for (int kk = 0; kk < 8; kk++) {
            uint32_t a[4];
            ldsm4(a, aBase + kk * 32);
#pragma unroll
            for (int ntp = 0; ntp < 4; ntp++) {
                uint32_t bb[4];
                ldsm4(bb, bBase + ntp * 16 * 272 + kk * 32);
                mma_tf32(c[2*ntp],   a, bb[0], bb[1]);
                mma_tf32(c[2*ntp+1], a, bb[2], bb[3]);
            }
        }

        // ---- epilogue: normalize + store ----
        {
            const int r0 = 16 * w + (l >> 2);
            const int r1 = r0 + 8;
            const float inv0 = 1.0f / (PN[r0 * 2] + PN[r0 * 2 + 1] + 1e-8f);
            const float inv1 = 1.0f / (PN[r1 * 2] + PN[r1 * 2 + 1] + 1e-8f);
            float* O0 = Ob + (size_t)(sbase + r0) * Dq + 2 * (l & 3);
            float* O1 = Ob + (size_t)(sbase + r1) * Dq + 2 * (l & 3);
#pragma unroll
            for (int j = 0; j < 8; j++) {
                *(float2*)(O0 + 8 * j) = make_float2(c[j][0] * inv0, c[j][1] * inv0);
                *(float2*)(O1 + 8 * j) = make_float2(c[j][2] * inv1, c[j][3] * inv1);
            }
        }
    }
}

// ---------------------------------------------------------------------------
extern "C" void kernel_launch(void* const* d_in, const int* in_sizes, int n_in,
                              void* d_out, int out_size)
{
    (void)in_sizes; (void)n_in; (void)out_size;
    const float* Q = (const float*)d_in[0];
    const float* K = (const float*)d_in[1];
    const float* V = (const float*)d_in[2];
    const float* M = (const float*)d_in[3];
    float* O = (float*)d_out;

    cudaFuncSetAttribute(k3_mma, cudaFuncAttributeMaxDynamicSharedMemorySize, SM3_SZ);

    k1_mma   <<<BHq * SPLIT1, 256>>>(K, V, M);
    k2_reduce<<<BHq,          256>>>();
    k3_mma   <<<BHq * SPLIT3, 256, SM3_SZ>>>(Q, M, O);
}

// round 15
// speedup vs baseline: 1.8046x; 1.0003x over previous
#include <cuda_runtime.h>
#include <cuda_bf16.h>
#include <cstdint>

#define Bq 4
#define Hq 16
#define Sq 4096
#define Dq 64
#define BHq (Bq*Hq)            // 64

#define SPLIT1 8
#define CHUNK1 (Sq/SPLIT1)     // 512 s-rows per pass-1 block
#define NT1    8               // tiles of 64 s
#define NPART  SPLIT1

#define SPLIT3 8
#define CHUNK3 (Sq/SPLIT3)     // 512 rows per pass-3 block
#define TILE3  128
#define NT3    (CHUNK3/TILE3)  // 4

__device__ float g_part[NPART][BHq][Dq*Dq];
__device__ float g_k1p [SPLIT1][BHq][Dq];
__device__ float g_kvT[BHq][Dq*Dq];   // kv transposed: [e][d]
__device__ float g_k1 [BHq][Dq];

__device__ __forceinline__ float phif(float x) {
    return x > 0.f ? x + 1.f : __expf(x);
}
#define SCALE 0.3535533905932738f  // 1/sqrt(sqrt(64))

__device__ __forceinline__ uint32_t s2u(const void* p) {
    uint32_t a;
    asm("{ .reg .u64 t; cvta.to.shared.u64 t, %1; cvt.u32.u64 %0, t; }"
        : "=r"(a) : "l"(p));
    return a;
}
__device__ __forceinline__ void ldsm4(uint32_t r[4], uint32_t addr) {
    asm volatile("ldmatrix.sync.aligned.m8n8.x4.shared.b16 {%0,%1,%2,%3}, [%4];"
                 : "=r"(r[0]), "=r"(r[1]), "=r"(r[2]), "=r"(r[3]) : "r"(addr));
}
__device__ __forceinline__ void mma_tf32(float c[4], const uint32_t a[4],
                                         uint32_t b0, uint32_t b1) {
    asm volatile(
        "mma.sync.aligned.m16n8k8.row.col.f32.tf32.tf32.f32 "
        "{%0,%1,%2,%3}, {%4,%5,%6,%7}, {%8,%9}, {%0,%1,%2,%3};"
        : "+f"(c[0]), "+f"(c[1]), "+f"(c[2]), "+f"(c[3])
        : "r"(a[0]), "r"(a[1]), "r"(a[2]), "r"(a[3]), "r"(b0), "r"(b1));
}
__device__ __forceinline__ uint32_t f2tf(float x) {
    uint32_t r;
    asm("cvt.rna.tf32.f32 %0, %1;" : "=r"(r) : "f"(x));
    return r;
}

// All smem tiles: row stride 68 u32 words (272 B: 272%128==16 -> ldsm rows
// conflict-free). 16B-chunk index XOR'd with (row>>3)&1 at store; ldsm
// lane addresses apply the matching XOR (derivation verified per group).

// ---------------------------------------------------------------------------
// Pass 1 (tf32 MMA): kv[d][e] = sum_s phi_k[s][d] v[s][e].
// Staging writes TRANSPOSED tf32 tiles kT[d][s], vT[e][s] (64x64, swizzled).
// 8 warps: warp w -> m-tile (d) = w>>1 (16 rows), n-half (e) = w&1 (32 cols).
// 8 k-steps (k8) per 64-s tile, 8 tiles.
// ---------------------------------------------------------------------------
__global__ void __launch_bounds__(256)
k1_mma(const float* __restrict__ K, const float* __restrict__ V,
       const float* __restrict__ mask)
{
    __shared__ uint32_t kT[64*68];
    __shared__ uint32_t vT[64*68];
    __shared__ float k1b[8][68];

    const int t  = threadIdx.x;
    const int w  = t >> 5, l = t & 31;
    const int bh = blockIdx.x & (BHq - 1);
    const int sp = blockIdx.x >> 6;
    const int b  = bh >> 4;
    const int s0 = sp * CHUNK1;

    const int r  = t >> 2;          // staged s-row in tile (0..63)
    const int qc = t & 3;           // d-block (16 elems)

    const int mt = w >> 1, nh = w & 1;
    const uint32_t uKT = s2u(kT), uVT = s2u(vT);
    // ldsm addressing with swizzle-compensated 16B selector
    const uint32_t aRow  = 16 * mt + (l & 15);
    const uint32_t selA  = ((l >> 4) & 1) ^ ((l >> 3) & 1);
    const uint32_t aBase = uKT + aRow * 272 + selA * 16;
    const uint32_t bRow  = 32 * nh + (l & 7) + 8 * ((l >> 4) & 1);
    const uint32_t selB  = ((l >> 3) & 1) ^ ((l >> 4) & 1);
    const uint32_t bBase = uVT + bRow * 272 + selB * 16;

    float c[4][4];
#pragma unroll
    for (int i = 0; i < 4; i++)
#pragma unroll
        for (int j = 0; j < 4; j++) c[i][j] = 0.f;
    float k1loc[16];
#pragma unroll
    for (int i = 0; i < 16; i++) k1loc[i] = 0.f;

    const float* Kb = K + (size_t)bh * Sq * Dq;
    const float* Vb = V + (size_t)bh * Sq * Dq;
    const float* Mb = mask + (size_t)b * Sq;

#pragma unroll 1
    for (int it = 0; it < NT1; it++) {
        const int s = s0 + it * 64 + r;
        float4 kk4[4], vv4[4];
#pragma unroll
        for (int c4 = 0; c4 < 4; c4++) {
            kk4[c4] = *(const float4*)(Kb + (size_t)s * Dq + 16 * qc + 4 * c4);
            vv4[c4] = *(const float4*)(Vb + (size_t)s * Dq + 16 * qc + 4 * c4);
        }
        const float m = Mb[s];

        __syncthreads();   // previous tile's ldsm reads complete

        // transposed swizzled stores: element d -> row d, s-word r
#pragma unroll
        for (int c4 = 0; c4 < 4; c4++) {
            const float kv_[4] = {kk4[c4].x, kk4[c4].y, kk4[c4].z, kk4[c4].w};
            const float vv_[4] = {vv4[c4].x, vv4[c4].y, vv4[c4].z, vv4[c4].w};
#pragma unroll
            for (int j = 0; j < 4; j++) {
                const int d  = 16 * qc + 4 * c4 + j;
                const int xr = ((4 * c4 + j) >> 3) & 1;   // = (d>>3)&1
                const int wd = d * 68 + ((((r >> 2) ^ xr) << 2) | (r & 3));
                const float p = phif(kv_[j] * SCALE) * m;
                k1loc[4 * c4 + j] += p;
                kT[wd] = f2tf(p);
                vT[wd] = f2tf(vv_[j]);
            }
        }
        __syncthreads();

#pragma unroll
        for (int kk = 0; kk < 8; kk++) {
            uint32_t a[4];
            ldsm4(a, aBase + kk * 32);
#pragma unroll
            for (int np = 0; np < 2; np++) {
                uint32_t bb[4];
                ldsm4(bb, bBase + np * 16 * 272 + kk * 32);
                mma_tf32(c[2*np],   a, bb[0], bb[1]);
                mma_tf32(c[2*np+1], a, bb[2], bb[3]);
            }
        }
    }

    // epilogue: kv partial
    float* dst = &g_part[sp][bh][0];
    const int r0 = 16 * mt + (l >> 2), r1 = r0 + 8;
#pragma unroll
    for (int nt = 0; nt < 4; nt++) {
        const int e = 32 * nh + 8 * nt + 2 * (l & 3);
        *(float2*)&dst[r0 * 64 + e] = make_float2(c[nt][0], c[nt][1]);
        *(float2*)&dst[r1 * 64 + e] = make_float2(c[nt][2], c[nt][3]);
    }

    // deterministic k_one reduction: warp xor-reduce over same-qc lanes
#pragma unroll
    for (int ofs = 4; ofs <= 16; ofs <<= 1)
#pragma unroll
        for (int i = 0; i < 16; i++)
            k1loc[i] += __shfl_xor_sync(0xffffffffu, k1loc[i], ofs);
    if (l < 4) {
#pragma unroll
        for (int i = 0; i < 16; i++) k1b[w][16 * l + i] = k1loc[i];
    }
    __syncthreads();
    if (t < Dq) {
        float s = 0.f;
#pragma unroll
        for (int ww = 0; ww < 8; ww++) s += k1b[ww][t];
        g_k1p[sp][bh][t] = s;
    }
}

// ---------------------------------------------------------------------------
// Pass 2: reduce partials; emit kvT[e][d] + k_one.
// ---------------------------------------------------------------------------
__global__ void __launch_bounds__(256)
k2_reduce()
{
    __shared__ float kvs[Dq][Dq + 1];
    const int bh = blockIdx.x;
    const int t  = threadIdx.x;

    for (int idx = t; idx < Dq * Dq; idx += 256) {
        float s = 0.f;
#pragma unroll
        for (int p = 0; p < NPART; p++) s += g_part[p][bh][idx];
        kvs[idx >> 6][idx & 63] = s;
    }
    if (t < Dq) {
        float s = 0.f;
#pragma unroll
        for (int p = 0; p < SPLIT1; p++) s += g_k1p[p][bh][t];
        g_k1[bh][t] = s;
    }
    __syncthreads();
    for (int idx = t; idx < Dq * Dq; idx += 256) {
        g_kvT[bh][idx] = kvs[idx & 63][idx >> 6];
    }
}

// ---------------------------------------------------------------------------
// Pass 3 (tf32 MMA): out = phi_q.kv / (phi_q.k_one + 1e-8).
// A = phi_q [s][d] row-major (natural), B = kvT [e][d] n-major (natural).
// Single tf32 term. 8 warps, warp w = m-tile (16 rows), full n=64.
// ---------------------------------------------------------------------------
#define SM3_A  0
#define SM3_B  (SM3_A + TILE3*68*4)         // 34816
#define SM3_PN (SM3_B + Dq*68*4)            // 52224: pnorm[128][2] f32
#define SM3_K1 (SM3_PN + TILE3*2*4)         // 53248
#define SM3_SZ (SM3_K1 + 256)               // 53504

__global__ void __launch_bounds__(256)
k3_mma(const float* __restrict__ Q, const float* __restrict__ mask,
       float* __restrict__ out)
{
    extern __shared__ char sm3[];
    const uint32_t sb = s2u(sm3);

    const int t  = threadIdx.x;
    const int w  = t >> 5, l = t & 31;
    const int bh = blockIdx.x >> 3;
    const int sp = blockIdx.x & 7;
    const int b  = bh >> 4;
    const int s0 = sp * CHUNK3;

    uint32_t* A = (uint32_t*)(sm3 + SM3_A);
    uint32_t* Bm = (uint32_t*)(sm3 + SM3_B);
    float* PN = (float*)(sm3 + SM3_PN);
    float* K1 = (float*)(sm3 + SM3_K1);

    // ---- stage B (kvT tf32, swizzled) + k1, once per block ----
    if (t < 128) {
        const int r = t >> 1, hf = t & 1;   // e row, d half
        const float* src = &g_kvT[bh][r * 64 + hf * 32];
        const int xr = (r >> 3) & 1;
#pragma unroll
        for (int cc = 0; cc < 8; cc++) {
            const float4 v = *(const float4*)(src + 4 * cc);
            const int chunk = (8 * hf + cc) ^ xr;
            *(uint4*)&Bm[r * 68 + 4 * chunk] =
                make_uint4(f2tf(v.x), f2tf(v.y), f2tf(v.z), f2tf(v.w));
        }
    }
    if (t < Dq) K1[t] = g_k1[bh][t];

    const float* Qb = Q + (size_t)bh * Sq * Dq;
    const float* Mb = mask + (size_t)b * Sq;
    float*       Ob = out + (size_t)bh * Sq * Dq;

    const uint32_t aRow  = 16 * w + (l & 15);
    const uint32_t selA  = ((l >> 4) & 1) ^ ((l >> 3) & 1);
    const uint32_t aBase = sb + SM3_A + aRow * 272 + selA * 16;
    const uint32_t bRow  = (l & 7) + 8 * ((l >> 4) & 1);
    const uint32_t selB  = ((l >> 3) & 1) ^ ((l >> 4) & 1);
    const uint32_t bBase = sb + SM3_B + bRow * 272 + selB * 16;

#pragma unroll 1
    for (int it = 0; it < NT3; it++) {
        const int sbase = s0 + it * TILE3;

        __syncthreads();   // previous tile's reads complete

        // ---- stage A tile (phi_q tf32, swizzled) + norm partials ----
        {
            const int r = t >> 1, hf = t & 1;
            const int row = sbase + r;
            const float m = Mb[row];
            const float* Qr = Qb + (size_t)row * Dq + hf * 32;
            const int xr = (r >> 3) & 1;
            float ns = 0.f;
#pragma unroll
            for (int cc = 0; cc < 8; cc++) {
                const float4 q = *(const float4*)(Qr + 4 * cc);
                const float p0 = phif(q.x * SCALE) * m;
                const float p1 = phif(q.y * SCALE) * m;
                const float p2 = phif(q.z * SCALE) * m;
                const float p3 = phif(q.w * SCALE) * m;
                const int chunk = (8 * hf + cc) ^ xr;
                *(uint4*)&A[r * 68 + 4 * chunk] =
                    make_uint4(f2tf(p0), f2tf(p1), f2tf(p2), f2tf(p3));
                const float* kc = K1 + hf * 32 + 4 * cc;
                ns += p0 * kc[0] + p1 * kc[1] + p2 * kc[2] + p3 * kc[3];
            }
            PN[r * 2 + hf] = ns;
        }
        __syncthreads();

        // ---- MMA mainloop: 8 k-steps x 8 n8-tiles, single tf32 term ----
        float c[8][4];
#pragma unroll
        for (int j = 0; j < 8; j++)
#pragma unroll
            for (int i = 0; i < 4; i++) c[j][i] = 0.f;

#pragma unroll
        for (int kk = 0; kk < 8; kk++) {
            uint32_t a[4];
            ldsm4(a, aBase + kk * 32);
#pragma unroll
            for (int ntp = 0; ntp < 4; ntp++) {
                uint32_t bb[4];
                ldsm4(bb, bBase + ntp * 16 * 272 + kk * 32);
                mma_tf32(c[2*ntp],   a, bb[0], bb[1]);
                mma_tf32(c[2*ntp+1], a, bb[2], bb[3]);
            }
        }

        // ---- epilogue: normalize + store ----
        {
            const int r0 = 16 * w + (l >> 2);
            const int r1 = r0 + 8;
            const float inv0 = 1.0f / (PN[r0 * 2] + PN[r0 * 2 + 1] + 1e-8f);
            const float inv1 = 1.0f / (PN[r1 * 2] + PN[r1 * 2 + 1] + 1e-8f);
            float* O0 = Ob + (size_t)(sbase + r0) * Dq + 2 * (l & 3);
            float* O1 = Ob + (size_t)(sbase + r1) * Dq + 2 * (l & 3);
#pragma unroll
            for (int j = 0; j < 8; j++) {
                *(float2*)(O0 + 8 * j) = make_float2(c[j][0] * inv0, c[j][1] * inv0);
                *(float2*)(O1 + 8 * j) = make_float2(c[j][2] * inv1, c[j][3] * inv1);
            }
        }
    }
}

// ---------------------------------------------------------------------------
extern "C" void kernel_launch(void* const* d_in, const int* in_sizes, int n_in,
                              void* d_out, int out_size)
{
    (void)in_sizes; (void)n_in; (void)out_size;
    const float* Q = (const float*)d_in[0];
    const float* K = (const float*)d_in[1];
    const float* V = (const float*)d_in[2];
    const float* M = (const float*)d_in[3];
    float* O = (float*)d_out;

    cudaFuncSetAttribute(k3_mma, cudaFuncAttributeMaxDynamicSharedMemorySize, SM3_SZ);

    k1_mma   <<<BHq * SPLIT1, 256>>>(K, V, M);
    k2_reduce<<<BHq,          256>>>();
    k3_mma   <<<BHq * SPLIT3, 256, SM3_SZ>>>(Q, M, O);
}